// round 6
// baseline (speedup 1.0000x reference)
#include <cuda_runtime.h>
#include <cstdint>

#define B        2
#define N_PRE    50000
#define N_POST   50000
#define N_SYN    10000000
#define N_TYPES  20
#define N_BASIS  5

#define MASK_WORDS (N_PRE / 16)          // 3125 words exactly (2 bits/neuron)
#define ROW_PAD    8                     // padded scratch row: 8 floats (32B)
#define SCRATCH_N  (B * N_POST * ROW_PAD)

__device__ uint32_t g_spike_mask[MASK_WORDS];
__device__ __align__(32) float g_scratch[SCRATCH_N];   // 3.2 MB, L2-resident

// ---------------------------------------------------------------------------
// prep: zero scratch (float4) + build packed 2-bit spike mask (float4 reads)
__global__ void prep_kernel(const float* __restrict__ spikes)
{
    int tid = blockIdx.x * blockDim.x + threadIdx.x;
    int nthreads = gridDim.x * blockDim.x;

    float4* s4 = (float4*)g_scratch;
    const int NS4 = SCRATCH_N / 4;                    // 200000
    for (int i = tid; i < NS4; i += nthreads)
        s4[i] = make_float4(0.f, 0.f, 0.f, 0.f);

    const float4* sp0 = (const float4*)spikes;                 // batch 0
    const float4* sp1 = (const float4*)(spikes + N_PRE);       // batch 1
    for (int w = tid; w < MASK_WORDS; w += nthreads) {
        uint32_t m = 0;
        #pragma unroll
        for (int q = 0; q < 4; q++) {                // 4 float4 per batch = 16 neurons
            float4 a = sp0[w * 4 + q];
            float4 b = sp1[w * 4 + q];
            int j = q * 4;
            m |= ((a.x != 0.f) ? 1u : 0u) << (2 * (j + 0));
            m |= ((a.y != 0.f) ? 1u : 0u) << (2 * (j + 1));
            m |= ((a.z != 0.f) ? 1u : 0u) << (2 * (j + 2));
            m |= ((a.w != 0.f) ? 1u : 0u) << (2 * (j + 3));
            m |= ((b.x != 0.f) ? 2u : 0u) << (2 * (j + 0));
            m |= ((b.y != 0.f) ? 2u : 0u) << (2 * (j + 1));
            m |= ((b.z != 0.f) ? 2u : 0u) << (2 * (j + 2));
            m |= ((b.w != 0.f) ? 2u : 0u) << (2 * (j + 3));
        }
        g_spike_mask[w] = m;
    }
}

// ---------------------------------------------------------------------------
__device__ __forceinline__ void red4(float* p, float c0, float c1, float c2, float c3)
{
    asm volatile("red.global.add.v4.f32 [%0], {%1, %2, %3, %4};"
                 :: "l"(p), "f"(c0), "f"(c1), "f"(c2), "f"(c3) : "memory");
}

// One firing synapse: lazy gathers + 2 reduction ops per firing batch.
__device__ __forceinline__ void emit_syn(uint32_t m, int syn, int post,
                                         const float* __restrict__ weights,
                                         const int*   __restrict__ syn_ids,
                                         const float* __restrict__ sb)
{
    if (m == 0u) return;
    float w = __ldg(weights + syn);
    int   t = __ldg(syn_ids + syn);
    const float* bt = sb + t * N_BASIS;
    float c0 = w * bt[0], c1 = w * bt[1], c2 = w * bt[2],
          c3 = w * bt[3], c4 = w * bt[4];
    if (m & 1u) {
        float* o = g_scratch + (size_t)post * ROW_PAD;
        red4(o, c0, c1, c2, c3);
        atomicAdd(o + 4, c4);
    }
    if (m & 2u) {
        float* o = g_scratch + ((size_t)N_POST + post) * ROW_PAD;
        red4(o, c0, c1, c2, c3);
        atomicAdd(o + 4, c4);
    }
}

__global__ __launch_bounds__(256)
void accum_kernel(const float* __restrict__ weights,       // [N_SYN]
                  const float* __restrict__ basis,         // [N_TYPES, N_BASIS]
                  const int4*  __restrict__ syn_idx4,      // [N_SYN/2]
                  const int*   __restrict__ syn_ids)       // [N_SYN]
{
    __shared__ uint32_t smask[MASK_WORDS];
    __shared__ float sb[N_TYPES * N_BASIS];

    for (int i = threadIdx.x; i < MASK_WORDS; i += blockDim.x)
        smask[i] = g_spike_mask[i];
    if (threadIdx.x < N_TYPES * N_BASIS) sb[threadIdx.x] = basis[threadIdx.x];
    __syncthreads();

    const int NG = N_SYN / 8;                 // 8 consecutive synapses / thread
    const int stride = gridDim.x * blockDim.x;

    for (int g = blockIdx.x * blockDim.x + threadIdx.x; g < NG; g += stride) {
        // 64 contiguous bytes of the index stream, streaming (evict-first),
        // front-batched for MLP=4.
        int4 u0 = __ldcs(syn_idx4 + g * 4);
        int4 u1 = __ldcs(syn_idx4 + g * 4 + 1);
        int4 u2 = __ldcs(syn_idx4 + g * 4 + 2);
        int4 u3 = __ldcs(syn_idx4 + g * 4 + 3);

        uint32_t m0 = (smask[u0.y >> 4] >> ((u0.y & 15) << 1)) & 3u;
        uint32_t m1 = (smask[u0.w >> 4] >> ((u0.w & 15) << 1)) & 3u;
        uint32_t m2 = (smask[u1.y >> 4] >> ((u1.y & 15) << 1)) & 3u;
        uint32_t m3 = (smask[u1.w >> 4] >> ((u1.w & 15) << 1)) & 3u;
        uint32_t m4 = (smask[u2.y >> 4] >> ((u2.y & 15) << 1)) & 3u;
        uint32_t m5 = (smask[u2.w >> 4] >> ((u2.w & 15) << 1)) & 3u;
        uint32_t m6 = (smask[u3.y >> 4] >> ((u3.y & 15) << 1)) & 3u;
        uint32_t m7 = (smask[u3.w >> 4] >> ((u3.w & 15) << 1)) & 3u;

        if ((m0 | m1 | m2 | m3 | m4 | m5 | m6 | m7) == 0u) continue;  // ~72%

        int s = g * 8;
        emit_syn(m0, s + 0, u0.x, weights, syn_ids, sb);
        emit_syn(m1, s + 1, u0.z, weights, syn_ids, sb);
        emit_syn(m2, s + 2, u1.x, weights, syn_ids, sb);
        emit_syn(m3, s + 3, u1.z, weights, syn_ids, sb);
        emit_syn(m4, s + 4, u2.x, weights, syn_ids, sb);
        emit_syn(m5, s + 5, u2.z, weights, syn_ids, sb);
        emit_syn(m6, s + 6, u3.x, weights, syn_ids, sb);
        emit_syn(m7, s + 7, u3.z, weights, syn_ids, sb);
    }
}

// ---------------------------------------------------------------------------
// compact: out[row][0..4] = scratch[row][0..4]; fully overwrites out.
__global__ void compact_kernel(float* __restrict__ out, int out_n)
{
    int k = blockIdx.x * blockDim.x + threadIdx.x;   // float4 index into out
    int n4 = out_n >> 2;
    if (k < n4) {
        float4 r;
        int j0 = k * 4;
        r.x = g_scratch[((j0 + 0) / N_BASIS) * ROW_PAD + (j0 + 0) % N_BASIS];
        r.y = g_scratch[((j0 + 1) / N_BASIS) * ROW_PAD + (j0 + 1) % N_BASIS];
        r.z = g_scratch[((j0 + 2) / N_BASIS) * ROW_PAD + (j0 + 2) % N_BASIS];
        r.w = g_scratch[((j0 + 3) / N_BASIS) * ROW_PAD + (j0 + 3) % N_BASIS];
        ((float4*)out)[k] = r;
    }
    // tail (out_n % 4)
    int tail_start = n4 * 4;
    int j = tail_start + k;
    if (k < out_n - tail_start)
        out[j] = g_scratch[(j / N_BASIS) * ROW_PAD + j % N_BASIS];
}

extern "C" void kernel_launch(void* const* d_in, const int* in_sizes, int n_in,
                              void* d_out, int out_size)
{
    const float* spikes  = (const float*)d_in[0];   // rec_z_buf [B, N_PRE]
    const float* weights = (const float*)d_in[1];   // weight_values [N_SYN]
    const float* basis   = (const float*)d_in[2];   // synaptic_basis_weights [20,5]
    const int4*  syn_idx = (const int4*)d_in[3];    // synapse_indices [N_SYN,2]
    const int*   syn_ids = (const int*)d_in[4];     // syn_ids [N_SYN]
    float* out = (float*)d_out;                     // [B*N_POST, N_BASIS]

    prep_kernel<<<512, 256>>>(spikes);

    accum_kernel<<<1184, 256>>>(weights, basis, syn_idx, syn_ids);

    {
        int n4 = (out_size >> 2) + 4;               // covers vector body + tail
        compact_kernel<<<(n4 + 255) / 256, 256>>>(out, out_size);
    }
}

// round 7
// speedup vs baseline: 1.1135x; 1.1135x over previous
#include <cuda_runtime.h>
#include <cstdint>

#define B        2
#define N_PRE    50000
#define N_POST   50000
#define N_SYN    10000000
#define N_TYPES  20
#define N_BASIS  5

#define MASK_WORDS (N_PRE / 16)          // 3125 words exactly (2 bits/neuron)
#define ROW_PAD    8                     // padded scratch row: 8 floats (32B)
#define SCRATCH_N  (B * N_POST * ROW_PAD)

__device__ uint32_t g_spike_mask[MASK_WORDS];
__device__ __align__(32) float g_scratch[SCRATCH_N];   // 3.2 MB, L2-resident

// ---------------------------------------------------------------------------
// prep: zero scratch (float4) + ballot-based packed 2-bit spike mask.
// One thread per neuron; warp ballots -> 2 packed words per warp.
__global__ void prep_kernel(const float* __restrict__ spikes)
{
    int tid = blockIdx.x * blockDim.x + threadIdx.x;
    int nthreads = gridDim.x * blockDim.x;

    // Mask build: neurons 0..N_PRE-1, one per thread (coalesced loads, depth-1 chain).
    if (tid < ((N_PRE + 31) & ~31)) {
        int n = tid;
        bool f0 = false, f1 = false;
        if (n < N_PRE) {
            f0 = (__ldg(spikes + n) != 0.0f);
            f1 = (__ldg(spikes + N_PRE + n) != 0.0f);
        }
        uint32_t b0 = __ballot_sync(0xFFFFFFFFu, f0);
        uint32_t b1 = __ballot_sync(0xFFFFFFFFu, f1);
        int lane = threadIdx.x & 31;
        // Each warp covers 32 neurons = 2 mask words (16 neurons each).
        if (lane == 0 || lane == 16) {
            uint32_t h0 = (b0 >> lane) & 0xFFFFu;
            uint32_t h1 = (b1 >> lane) & 0xFFFFu;
            uint32_t m = 0;
            #pragma unroll
            for (int j = 0; j < 16; j++)
                m |= (((h0 >> j) & 1u) | (((h1 >> j) & 1u) << 1)) << (2 * j);
            int w = (n >> 4);            // n = 32*warp + lane; lane 0/16 -> word index
            if (w < MASK_WORDS) g_spike_mask[w] = m;
        }
    }

    // Zero scratch via float4 (3.2 MB, lands in L2).
    float4* s4 = (float4*)g_scratch;
    const int NS4 = SCRATCH_N / 4;                    // 200000
    for (int i = tid; i < NS4; i += nthreads)
        s4[i] = make_float4(0.f, 0.f, 0.f, 0.f);
}

// ---------------------------------------------------------------------------
__device__ __forceinline__ void red4(float* p, float c0, float c1, float c2, float c3)
{
    asm volatile("red.global.add.v4.f32 [%0], {%1, %2, %3, %4};"
                 :: "l"(p), "f"(c0), "f"(c1), "f"(c2), "f"(c3) : "memory");
}

// One firing synapse: lazy gathers + 2 reduction ops per firing batch.
__device__ __forceinline__ void emit_syn(uint32_t m, int syn, int post,
                                         const float* __restrict__ weights,
                                         const int*   __restrict__ syn_ids,
                                         const float* __restrict__ sb)
{
    if (m == 0u) return;
    float w = __ldg(weights + syn);
    int   t = __ldg(syn_ids + syn);
    const float* bt = sb + t * N_BASIS;
    float c0 = w * bt[0], c1 = w * bt[1], c2 = w * bt[2],
          c3 = w * bt[3], c4 = w * bt[4];
    if (m & 1u) {
        float* o = g_scratch + (size_t)post * ROW_PAD;
        red4(o, c0, c1, c2, c3);
        atomicAdd(o + 4, c4);
    }
    if (m & 2u) {
        float* o = g_scratch + ((size_t)N_POST + post) * ROW_PAD;
        red4(o, c0, c1, c2, c3);
        atomicAdd(o + 4, c4);
    }
}

__global__ __launch_bounds__(256)
void accum_kernel(const float* __restrict__ weights,       // [N_SYN]
                  const float* __restrict__ basis,         // [N_TYPES, N_BASIS]
                  const int4*  __restrict__ syn_idx4,      // [N_SYN/2]
                  const int*   __restrict__ syn_ids)       // [N_SYN]
{
    __shared__ uint32_t smask[MASK_WORDS];
    __shared__ float sb[N_TYPES * N_BASIS];

    for (int i = threadIdx.x; i < MASK_WORDS; i += blockDim.x)
        smask[i] = g_spike_mask[i];
    if (threadIdx.x < N_TYPES * N_BASIS) sb[threadIdx.x] = basis[threadIdx.x];
    __syncthreads();

    const int NG = N_SYN / 4;                 // 4 consecutive synapses / thread
    const int stride = gridDim.x * blockDim.x;

    for (int g = blockIdx.x * blockDim.x + threadIdx.x; g < NG; g += stride) {
        // 32 contiguous bytes of the index stream, streaming (evict-first).
        int4 u = __ldcs(syn_idx4 + g * 2);     // syn 4g+0:(u.x,u.y) 4g+1:(u.z,u.w)
        int4 v = __ldcs(syn_idx4 + g * 2 + 1); // syn 4g+2:(v.x,v.y) 4g+3:(v.z,v.w)

        uint32_t m0 = (smask[u.y >> 4] >> ((u.y & 15) << 1)) & 3u;
        uint32_t m1 = (smask[u.w >> 4] >> ((u.w & 15) << 1)) & 3u;
        uint32_t m2 = (smask[v.y >> 4] >> ((v.y & 15) << 1)) & 3u;
        uint32_t m3 = (smask[v.w >> 4] >> ((v.w & 15) << 1)) & 3u;

        if ((m0 | m1 | m2 | m3) == 0u) continue;   // ~85% of groups

        int s = g * 4;
        emit_syn(m0, s + 0, u.x, weights, syn_ids, sb);
        emit_syn(m1, s + 1, u.z, weights, syn_ids, sb);
        emit_syn(m2, s + 2, v.x, weights, syn_ids, sb);
        emit_syn(m3, s + 3, v.z, weights, syn_ids, sb);
    }
}

// ---------------------------------------------------------------------------
// compact: out[row][0..4] = scratch[row][0..4]; fully overwrites out.
__global__ void compact_kernel(float* __restrict__ out, int out_n)
{
    int k = blockIdx.x * blockDim.x + threadIdx.x;   // float4 index into out
    int n4 = out_n >> 2;
    if (k < n4) {
        float4 r;
        int j0 = k * 4;
        r.x = g_scratch[((j0 + 0) / N_BASIS) * ROW_PAD + (j0 + 0) % N_BASIS];
        r.y = g_scratch[((j0 + 1) / N_BASIS) * ROW_PAD + (j0 + 1) % N_BASIS];
        r.z = g_scratch[((j0 + 2) / N_BASIS) * ROW_PAD + (j0 + 2) % N_BASIS];
        r.w = g_scratch[((j0 + 3) / N_BASIS) * ROW_PAD + (j0 + 3) % N_BASIS];
        ((float4*)out)[k] = r;
    }
    // tail (out_n % 4)
    int tail_start = n4 * 4;
    int j = tail_start + k;
    if (k < out_n - tail_start)
        out[j] = g_scratch[(j / N_BASIS) * ROW_PAD + j % N_BASIS];
}

extern "C" void kernel_launch(void* const* d_in, const int* in_sizes, int n_in,
                              void* d_out, int out_size)
{
    const float* spikes  = (const float*)d_in[0];   // rec_z_buf [B, N_PRE]
    const float* weights = (const float*)d_in[1];   // weight_values [N_SYN]
    const float* basis   = (const float*)d_in[2];   // synaptic_basis_weights [20,5]
    const int4*  syn_idx = (const int4*)d_in[3];    // synapse_indices [N_SYN,2]
    const int*   syn_ids = (const int*)d_in[4];     // syn_ids [N_SYN]
    float* out = (float*)d_out;                     // [B*N_POST, N_BASIS]

    prep_kernel<<<512, 256>>>(spikes);

    accum_kernel<<<1184, 256>>>(weights, basis, syn_idx, syn_ids);

    {
        int n4 = (out_size >> 2) + 4;               // covers vector body + tail
        compact_kernel<<<(n4 + 255) / 256, 256>>>(out, out_size);
    }
}

// round 8
// speedup vs baseline: 1.1860x; 1.0650x over previous
#include <cuda_runtime.h>
#include <cstdint>

#define B        2
#define N_PRE    50000
#define N_POST   50000
#define N_SYN    10000000
#define N_TYPES  20
#define N_BASIS  5

#define MASK_WORDS (N_PRE / 16)          // 3125 words (2 bits/neuron)
#define N_ROWS     (B * N_POST)          // 100000

__device__ uint32_t g_spike_mask[MASK_WORDS];
// Per-(batch,post) x type weight sums. Zero at module load; compact_kernel
// re-zeroes after reading, so it is zero at entry of EVERY kernel_launch call.
__device__ __align__(16) float g_S[N_ROWS * N_TYPES];   // 8 MB, L2-resident

// ---------------------------------------------------------------------------
// prep: ballot-based packed 2-bit spike mask only (no zeroing needed).
__global__ void prep_kernel(const float* __restrict__ spikes)
{
    int tid = blockIdx.x * blockDim.x + threadIdx.x;
    if (tid >= ((N_PRE + 31) & ~31)) return;
    int n = tid;
    bool f0 = false, f1 = false;
    if (n < N_PRE) {
        f0 = (__ldg(spikes + n) != 0.0f);
        f1 = (__ldg(spikes + N_PRE + n) != 0.0f);
    }
    uint32_t b0 = __ballot_sync(0xFFFFFFFFu, f0);
    uint32_t b1 = __ballot_sync(0xFFFFFFFFu, f1);
    int lane = threadIdx.x & 31;
    if (lane == 0 || lane == 16) {
        uint32_t h0 = (b0 >> lane) & 0xFFFFu;
        uint32_t h1 = (b1 >> lane) & 0xFFFFu;
        uint32_t m = 0;
        #pragma unroll
        for (int j = 0; j < 16; j++)
            m |= (((h0 >> j) & 1u) | (((h1 >> j) & 1u) << 1)) << (2 * j);
        int w = (n >> 4);
        if (w < MASK_WORDS) g_spike_mask[w] = m;
    }
}

// ---------------------------------------------------------------------------
// One firing synapse: 2 lazy gathers + <=2 scalar reductions into S.
__device__ __forceinline__ void emit_syn(uint32_t m, int syn, int post,
                                         const float* __restrict__ weights,
                                         const int*   __restrict__ syn_ids)
{
    if (m == 0u) return;
    float w = __ldg(weights + syn);
    int   t = __ldg(syn_ids + syn);
    if (m & 1u) atomicAdd(g_S + (size_t)post * N_TYPES + t, w);
    if (m & 2u) atomicAdd(g_S + ((size_t)N_POST + post) * N_TYPES + t, w);
}

__global__ __launch_bounds__(256)
void accum_kernel(const float* __restrict__ weights,       // [N_SYN]
                  const int4*  __restrict__ syn_idx4,      // [N_SYN/2]
                  const int*   __restrict__ syn_ids)       // [N_SYN]
{
    __shared__ uint32_t smask[MASK_WORDS];
    for (int i = threadIdx.x; i < MASK_WORDS; i += blockDim.x)
        smask[i] = g_spike_mask[i];
    __syncthreads();

    const int NG = N_SYN / 4;                 // 4 consecutive synapses / thread
    const int stride = gridDim.x * blockDim.x;

    for (int g = blockIdx.x * blockDim.x + threadIdx.x; g < NG; g += stride) {
        int4 u = __ldcs(syn_idx4 + g * 2);     // syn 4g+0:(u.x,u.y) 4g+1:(u.z,u.w)
        int4 v = __ldcs(syn_idx4 + g * 2 + 1); // syn 4g+2:(v.x,v.y) 4g+3:(v.z,v.w)

        uint32_t m0 = (smask[u.y >> 4] >> ((u.y & 15) << 1)) & 3u;
        uint32_t m1 = (smask[u.w >> 4] >> ((u.w & 15) << 1)) & 3u;
        uint32_t m2 = (smask[v.y >> 4] >> ((v.y & 15) << 1)) & 3u;
        uint32_t m3 = (smask[v.w >> 4] >> ((v.w & 15) << 1)) & 3u;

        if ((m0 | m1 | m2 | m3) == 0u) continue;   // ~85% of groups

        int s = g * 4;
        emit_syn(m0, s + 0, u.x, weights, syn_ids);
        emit_syn(m1, s + 1, u.z, weights, syn_ids);
        emit_syn(m2, s + 2, v.x, weights, syn_ids);
        emit_syn(m3, s + 3, v.z, weights, syn_ids);
    }
}

// ---------------------------------------------------------------------------
// compact: out[row][r] = sum_t S[row][t] * basis[t][r]; then zero S[row].
// Block handles 256 rows -> 1280 contiguous out floats, staged in smem for
// coalesced float4 stores. Each row's S is read and zeroed by its owner
// thread only (no race).
__global__ __launch_bounds__(256)
void compact_kernel(const float* __restrict__ basis, float* __restrict__ out)
{
    __shared__ float sb[N_TYPES * N_BASIS];
    __shared__ float srow[256 * N_BASIS];

    int tid = threadIdx.x;
    if (tid < N_TYPES * N_BASIS) sb[tid] = basis[tid];
    __syncthreads();

    int row = blockIdx.x * 256 + tid;
    if (row < N_ROWS) {
        float4* S4 = (float4*)(g_S + (size_t)row * N_TYPES);   // 20 floats, 16B-aligned
        float4 a = S4[0], b = S4[1], c = S4[2], d = S4[3], e = S4[4];
        float s[N_TYPES] = {a.x,a.y,a.z,a.w, b.x,b.y,b.z,b.w, c.x,c.y,c.z,c.w,
                            d.x,d.y,d.z,d.w, e.x,e.y,e.z,e.w};
        #pragma unroll
        for (int r = 0; r < N_BASIS; r++) {
            float acc = 0.f;
            #pragma unroll
            for (int t = 0; t < N_TYPES; t++)
                acc += s[t] * sb[t * N_BASIS + r];
            srow[tid * N_BASIS + r] = acc;
        }
        // Re-zero S for the next kernel_launch call (invariant).
        float4 z = make_float4(0.f, 0.f, 0.f, 0.f);
        S4[0] = z; S4[1] = z; S4[2] = z; S4[3] = z; S4[4] = z;
    }
    __syncthreads();

    // Coalesced stores: this block owns out floats [blk*1280, blk*1280+1280).
    const int total4 = (N_ROWS * N_BASIS) / 4;        // 125000 float4
    int base4 = blockIdx.x * 320;
    float4* out4 = (float4*)out;
    for (int i = tid; i < 320; i += 256) {
        int o4 = base4 + i;
        if (o4 < total4) {
            const float* p = srow + i * 4;
            out4[o4] = make_float4(p[0], p[1], p[2], p[3]);
        }
    }
}

extern "C" void kernel_launch(void* const* d_in, const int* in_sizes, int n_in,
                              void* d_out, int out_size)
{
    const float* spikes  = (const float*)d_in[0];   // rec_z_buf [B, N_PRE]
    const float* weights = (const float*)d_in[1];   // weight_values [N_SYN]
    const float* basis   = (const float*)d_in[2];   // synaptic_basis_weights [20,5]
    const int4*  syn_idx = (const int4*)d_in[3];    // synapse_indices [N_SYN,2]
    const int*   syn_ids = (const int*)d_in[4];     // syn_ids [N_SYN]
    float* out = (float*)d_out;                     // [B*N_POST, N_BASIS]

    prep_kernel<<<196, 256>>>(spikes);

    accum_kernel<<<1184, 256>>>(weights, syn_idx, syn_ids);

    compact_kernel<<<(N_ROWS + 255) / 256, 256>>>(basis, out);
}